// round 15
// baseline (speedup 1.0000x reference)
#include <cuda_runtime.h>
#include <cuda_fp16.h>
#include <cstdint>

// Problem constants
#define HWDIM 9216            // H*W = 96*96
#define NB 16                 // batch
#define NPOS (HWDIM * NB)     // 147456 spatial positions
#define CIN 256
#define HCH 10                // h
#define NPARTS 6
#define PART_SZ (NPARTS * NB * HCH * HWDIM)   // 8,847,360 (fits int)
#define PBH (NB * HCH * HWDIM)                // 1,474,560

#define NCHUNK 4
#define POS_PER_CHUNK (NPOS / NCHUNK)         // 36864
#define GEMM_CTAS_PER_CHUNK (POS_PER_CHUNK / 128)  // 288
#define EPI_CTAS_PER_CHUNK  (POS_PER_CHUNK / 256)  // 144

typedef unsigned long long u64;

// Scratch: Y[k][n] in fp16 (k = 0..9 fdp rows, 10..69 proj rows), 20.6 MB
__device__ __half g_Y[(size_t)70 * NPOS];

// Pre-packed tf32 weights: 72 rows x 264 words (pair-packed for LDS.64 frags)
#define B_STRIDE 264
#define B_WORDS (72 * B_STRIDE)      // 19008
__device__ uint32_t g_Bw[B_WORDS];

__device__ __forceinline__ float sigm(float x) {
    return 1.0f / (1.0f + __expf(-x));
}

__device__ __forceinline__ uint32_t to_tf32(float x) {
    uint32_t r;
    asm("cvt.rna.tf32.f32 %0, %1;" : "=r"(r) : "f"(x));
    return r;
}

__device__ __forceinline__ void mma_tf32(float d[4],
                                         uint32_t a0, uint32_t a1,
                                         uint32_t a2, uint32_t a3,
                                         uint32_t b0, uint32_t b1) {
    asm volatile(
        "mma.sync.aligned.m16n8k8.row.col.f32.tf32.tf32.f32 "
        "{%0,%1,%2,%3}, {%4,%5,%6,%7}, {%8,%9}, {%0,%1,%2,%3};"
        : "+f"(d[0]), "+f"(d[1]), "+f"(d[2]), "+f"(d[3])
        : "r"(a0), "r"(a1), "r"(a2), "r"(a3), "r"(b0), "r"(b1));
}

// ---------------------------------------------------------------------------
// Prep kernel: tf32 weights, pair-packed layout.
// ---------------------------------------------------------------------------
__global__ void prep_kernel(const float* __restrict__ w_dp_f,
                            const float* __restrict__ w_proj) {
    const int r = blockIdx.x;          // 0..71
    const int k = threadIdx.x;         // 0..255
    float v = 0.f;
    if (r < HCH)      v = w_dp_f[r * CIN + k];
    else if (r < 70)  v = w_proj[(r - HCH) * CIN + k];
    g_Bw[r * B_STRIDE + ((k >> 3) << 3) + (k & 3) * 2 + ((k >> 2) & 1)] = to_tf32(v);
    if (k < 8) g_Bw[r * B_STRIDE + 256 + k] = 0u;
}

// ---------------------------------------------------------------------------
// Kernel A (round-14 exact + tile offset): mma.sync tf32, 128 pos/CTA,
// double-buffered A, fp16 Y stores.
// ---------------------------------------------------------------------------
#define A_STRIDE 136
#define A_WORDS (64 * A_STRIDE)                       // 8704 per buffer
#define GEMM_SMEM ((B_WORDS + 2 * A_WORDS) * 4)       // 145,664 bytes

extern __shared__ uint32_t sm4[];

__global__ void __launch_bounds__(256, 1)
gemm_tc(const float* __restrict__ p_fea, int tile0) {
    const int tid  = threadIdx.x;
    const int wid  = tid >> 5;
    const int lane = tid & 31;

    {
        uint4* dst = (uint4*)sm4;
        const uint4* src = (const uint4*)g_Bw;
#pragma unroll
        for (int i = 0; i < 19; ++i) {
            const int idx = tid + i * 256;
            if (idx < B_WORDS / 4) dst[idx] = src[idx];
        }
    }

    const int tbase = (tile0 + blockIdx.x) * 128;
    const int b  = tbase / HWDIM;
    const int s0 = tbase - b * HWDIM;

    const int pos = tid & 127;
    const int kb  = tid >> 7;
    const float* gx = p_fea + (size_t)b * (CIN * HWDIM) + s0 + pos;

    const int mt = wid;
    const int q  = lane >> 2;
    const int rr = lane & 3;
    const int arow = mt * 16 + q;

    float d[9][4];
#pragma unroll
    for (int nt = 0; nt < 9; ++nt)
#pragma unroll
        for (int j = 0; j < 4; ++j) d[nt][j] = 0.f;

    uint32_t* Abuf0 = sm4 + B_WORDS;

    float xr[32];
#pragma unroll
    for (int i = 0; i < 32; ++i)
        xr[i] = gx[(size_t)(kb + i * 2) * HWDIM];
#pragma unroll
    for (int i = 0; i < 32; ++i)
        Abuf0[(kb + i * 2) * A_STRIDE + pos] = to_tf32(xr[i]);

#pragma unroll 1
    for (int c = 0; c < 4; ++c) {
        uint32_t* Ac = sm4 + B_WORDS + (c & 1) * A_WORDS;
        uint32_t* An = sm4 + B_WORDS + ((c + 1) & 1) * A_WORDS;

        if (c < 3) {
#pragma unroll
            for (int i = 0; i < 32; ++i)
                xr[i] = gx[(size_t)((c + 1) * 64 + kb + i * 2) * HWDIM];
        }
        __syncthreads();

#pragma unroll
        for (int ks = 0; ks < 8; ++ks) {
            const int kl = ks * 8 + rr;
            const uint32_t a0 = Ac[kl * A_STRIDE + arow];
            const uint32_t a1 = Ac[kl * A_STRIDE + arow + 8];
            const uint32_t a2 = Ac[(kl + 4) * A_STRIDE + arow];
            const uint32_t a3 = Ac[(kl + 4) * A_STRIDE + arow + 8];
            const int bbase = (c * 8 + ks) * 8 + rr * 2;
#pragma unroll
            for (int nt = 0; nt < 9; ++nt) {
                const u64 b01 = *(const u64*)(sm4 + (nt * 8 + q) * B_STRIDE + bbase);
                mma_tf32(d[nt], a0, a1, a2, a3,
                         (uint32_t)b01, (uint32_t)(b01 >> 32));
            }
        }

        if (c < 3) {
#pragma unroll
            for (int i = 0; i < 32; ++i)
                An[(kb + i * 2) * A_STRIDE + pos] = to_tf32(xr[i]);
        }
    }

    const int pbase = tbase + mt * 16 + q;
#pragma unroll
    for (int nt = 0; nt < 9; ++nt) {
        const int n0 = nt * 8 + rr * 2;
        if (n0 < 70) {
            g_Y[n0 * NPOS + pbase]     = __float2half(d[nt][0]);
            g_Y[n0 * NPOS + pbase + 8] = __float2half(d[nt][2]);
        }
        if (n0 + 1 < 70) {
            g_Y[(n0 + 1) * NPOS + pbase]     = __float2half(d[nt][1]);
            g_Y[(n0 + 1) * NPOS + pbase + 8] = __float2half(d[nt][3]);
        }
    }
}

// ---------------------------------------------------------------------------
// Kernel B (round-14 exact + block offset): epilogue with smem xq cache.
// ---------------------------------------------------------------------------
#define EPI_CW 2224
#define EPI_SMEM ((EPI_CW + 60 * 256) * 4)    // 70,336 bytes

__global__ void __launch_bounds__(256, 2)
epi_kernel(const float* __restrict__ xp_stack,
           const float* __restrict__ xh_stack,
           const float* __restrict__ w_att,  const float* __restrict__ b_att,
           const float* __restrict__ w_dp_x, const float* __restrict__ b_dp,
           const float* __restrict__ b_proj,
           const float* __restrict__ w_gate, const float* __restrict__ b_gate,
           const float* __restrict__ w_upd,  const float* __restrict__ b_upd,
           float* __restrict__ out, int blk0) {
    float* cw  = (float*)sm4;
    float* xqc = cw + EPI_CW;
    const int tid = threadIdx.x;

    for (int i = tid; i < 2222; i += 256) {
        float v;
        if      (i < 60)   v = w_att[i];
        else if (i < 66)   v = b_att[i - 60];
        else if (i < 166)  v = w_dp_x[i - 66];
        else if (i < 176)  v = b_dp[i - 166];
        else if (i < 236)  v = b_proj[i - 176];
        else if (i < 356)  v = w_gate[i - 236];
        else if (i < 362)  v = b_gate[i - 356];
        else if (i < 2162) v = w_upd[i - 362];
        else               v = b_upd[i - 2162];
        cw[i] = v;
    }
    __syncthreads();

    const float* sW_att  = cw;
    const float* sB_att  = cw + 60;
    const float* sW_dpx  = cw + 66;
    const float* sB_dp   = cw + 166;
    const float* sB_proj = cw + 176;
    const float* sW_gate = cw + 236;
    const float* sB_gate = cw + 356;
    const float* sW_upd  = cw + 362;
    const float* sB_upd  = cw + 2162;

    const int n = (blk0 + blockIdx.x) * 256 + tid;
    const int b = n / HWDIM;
    const int s = n - b * HWDIM;
    const int bbase = b * (HCH * HWDIM) + s;

    float fdp[HCH];
#pragma unroll
    for (int d = 0; d < HCH; ++d)
        fdp[d] = __half2float(g_Y[d * NPOS + n]) + sB_dp[d];

    float att[NPARTS];
    float dp1[HCH], S[HCH], xp1[HCH];
    float attsum = 0.f;
#pragma unroll
    for (int d = 0; d < HCH; ++d) S[d] = 0.f;

    // ---- pass 1: load xq from gmem once, stash in smem
#pragma unroll
    for (int p = 0; p < NPARTS; ++p) {
        const float* xpp_ptr = xp_stack + p * PBH + bbase;
        float xq[HCH];
#pragma unroll
        for (int d = 0; d < HCH; ++d) {
            xq[d] = xpp_ptr[d * HWDIM];
            xqc[(p * HCH + d) * 256 + tid] = xq[d];
        }

        float a = sB_att[p];
#pragma unroll
        for (int d = 0; d < HCH; ++d) a += sW_att[p * HCH + d] * xq[d];
        a = sigm(a);
        att[p] = a;

        float dpv[HCH];
#pragma unroll
        for (int d = 0; d < HCH; ++d) {
            float u = fdp[d];
#pragma unroll
            for (int e = 0; e < HCH; ++e) u += sW_dpx[d * HCH + e] * xq[e];
            dpv[d] = fmaxf(u, 0.f);
        }
        if (p == 1) {
#pragma unroll
            for (int d = 0; d < HCH; ++d) { dp1[d] = dpv[d]; xp1[d] = xq[d]; }
        } else {
            attsum += a;
#pragma unroll
            for (int d = 0; d < HCH; ++d) S[d] += a * dpv[d];
        }
    }

    // ---- pass 2: xq from smem
#pragma unroll
    for (int p = 0; p < NPARTS; ++p) {
        float xq[HCH];
        if (p == 1) {
#pragma unroll
            for (int d = 0; d < HCH; ++d) xq[d] = xp1[d];
        } else {
#pragma unroll
            for (int d = 0; d < HCH; ++d) xq[d] = xqc[(p * HCH + d) * 256 + tid];
        }

        float xppv[HCH];
        if (p == 1) {
#pragma unroll
            for (int d = 0; d < HCH; ++d)
                xppv[d] = att[1] * (S[d] + attsum * xp1[d]);
        } else {
            const float aa = att[1] * att[p];
#pragma unroll
            for (int d = 0; d < HCH; ++d)
                xppv[d] = aa * (dp1[d] + xq[d]);
        }

        const int hf = (p < 4) ? 0 : 1;
        const float* xh_ptr = xh_stack + hf * PBH + bbase;
        float gsum = sB_gate[p];
#pragma unroll
        for (int d = 0; d < HCH; ++d)
            gsum += sW_gate[p * 2 * HCH + d] * xh_ptr[d * HWDIM];
#pragma unroll
        for (int d = 0; d < HCH; ++d)
            gsum += sW_gate[p * 2 * HCH + HCH + d] * xq[d];
        const float gate = sigm(gsum);

        float xhpv[HCH];
#pragma unroll
        for (int d = 0; d < HCH; ++d)
            xhpv[d] = gate * (__half2float(g_Y[(HCH + p * HCH + d) * NPOS + n])
                              + sB_proj[p * HCH + d]);

        float* o0 = out + p * PBH + bbase;
#pragma unroll
        for (int d = 0; d < HCH; ++d) {
            float u = sB_upd[p * HCH + d];
            const float* wr = sW_upd + (p * HCH + d) * (3 * HCH);
#pragma unroll
            for (int e = 0; e < HCH; ++e) u += wr[e] * xq[e];
#pragma unroll
            for (int e = 0; e < HCH; ++e) u += wr[HCH + e] * xppv[e];
#pragma unroll
            for (int e = 0; e < HCH; ++e) u += wr[2 * HCH + e] * xhpv[e];
            const float o = xq[d] + fmaxf(u, 0.f);

            const int doff = d * HWDIM;
            o0[doff]                = o;
            o0[PART_SZ + doff]      = xppv[d];
            o0[2 * PART_SZ + doff]  = xhpv[d];
        }
    }
}

// ---------------------------------------------------------------------------
// Launch: chunked gemm on the capture (legacy) stream, epi chunks on a
// forked non-blocking stream released per-chunk via events -> overlap.
// ---------------------------------------------------------------------------
extern "C" void kernel_launch(void* const* d_in, const int* in_sizes, int n_in,
                              void* d_out, int out_size) {
    const float* p_fea  = (const float*)d_in[0];
    const float* xp     = (const float*)d_in[1];
    const float* xh     = (const float*)d_in[2];
    const float* w_att  = (const float*)d_in[3];
    const float* b_att  = (const float*)d_in[4];
    const float* w_dp_f = (const float*)d_in[5];
    const float* w_dp_x = (const float*)d_in[6];
    const float* b_dp   = (const float*)d_in[7];
    const float* w_proj = (const float*)d_in[8];
    const float* b_proj = (const float*)d_in[9];
    const float* w_gate = (const float*)d_in[10];
    const float* b_gate = (const float*)d_in[11];
    const float* w_upd  = (const float*)d_in[12];
    const float* b_upd  = (const float*)d_in[13];
    float* out = (float*)d_out;

    cudaFuncSetAttribute(gemm_tc, cudaFuncAttributeMaxDynamicSharedMemorySize,
                         GEMM_SMEM);
    cudaFuncSetAttribute(epi_kernel, cudaFuncAttributeMaxDynamicSharedMemorySize,
                         EPI_SMEM);

    cudaStream_t sB;
    cudaStreamCreateWithFlags(&sB, cudaStreamNonBlocking);
    cudaEvent_t ev[NCHUNK], evJoin;
    for (int c = 0; c < NCHUNK; ++c)
        cudaEventCreateWithFlags(&ev[c], cudaEventDisableTiming);
    cudaEventCreateWithFlags(&evJoin, cudaEventDisableTiming);

    prep_kernel<<<72, 256>>>(w_dp_f, w_proj);

    for (int c = 0; c < NCHUNK; ++c) {
        gemm_tc<<<GEMM_CTAS_PER_CHUNK, 256, GEMM_SMEM>>>(
            p_fea, c * GEMM_CTAS_PER_CHUNK);
        cudaEventRecord(ev[c], 0);
        cudaStreamWaitEvent(sB, ev[c], 0);
        epi_kernel<<<EPI_CTAS_PER_CHUNK, 256, EPI_SMEM, sB>>>(
            xp, xh, w_att, b_att, w_dp_x, b_dp, b_proj,
            w_gate, b_gate, w_upd, b_upd, out, c * EPI_CTAS_PER_CHUNK);
    }

    cudaEventRecord(evJoin, sB);
    cudaStreamWaitEvent(0, evJoin, 0);

    for (int c = 0; c < NCHUNK; ++c) cudaEventDestroy(ev[c]);
    cudaEventDestroy(evJoin);
    cudaStreamDestroy(sB);
}

// round 16
// speedup vs baseline: 1.3107x; 1.3107x over previous
#include <cuda_runtime.h>
#include <cuda_fp16.h>
#include <cstdint>

// Problem constants
#define HWDIM 9216            // H*W = 96*96
#define NB 16                 // batch
#define NPOS (HWDIM * NB)     // 147456 spatial positions
#define CIN 256
#define HCH 10                // h
#define NPARTS 6
#define PART_SZ (NPARTS * NB * HCH * HWDIM)   // 8,847,360 (fits int)
#define PBH (NB * HCH * HWDIM)                // 1,474,560

#define GEMM_GRID 144
#define TILES_PER_CTA 8       // 144*8 = 1152 tiles of 128 positions

typedef unsigned long long u64;

// Scratch: Y[k][n] in fp16 (k = 0..9 fdp rows, 10..69 proj rows), 20.6 MB
__device__ __half g_Y[(size_t)70 * NPOS];

// Pre-packed tf32 weights: 72 rows x 264 words (pair-packed for LDS.64 frags)
#define B_STRIDE 264
#define B_WORDS (72 * B_STRIDE)      // 19008
__device__ uint32_t g_Bw[B_WORDS];

__device__ __forceinline__ float sigm(float x) {
    return 1.0f / (1.0f + __expf(-x));
}

__device__ __forceinline__ uint32_t to_tf32(float x) {
    uint32_t r;
    asm("cvt.rna.tf32.f32 %0, %1;" : "=r"(r) : "f"(x));
    return r;
}

__device__ __forceinline__ void mma_tf32(float d[4],
                                         uint32_t a0, uint32_t a1,
                                         uint32_t a2, uint32_t a3,
                                         uint32_t b0, uint32_t b1) {
    asm volatile(
        "mma.sync.aligned.m16n8k8.row.col.f32.tf32.tf32.f32 "
        "{%0,%1,%2,%3}, {%4,%5,%6,%7}, {%8,%9}, {%0,%1,%2,%3};"
        : "+f"(d[0]), "+f"(d[1]), "+f"(d[2]), "+f"(d[3])
        : "r"(a0), "r"(a1), "r"(a2), "r"(a3), "r"(b0), "r"(b1));
}

// ---------------------------------------------------------------------------
// Prep kernel: tf32 weights, pair-packed layout.
// ---------------------------------------------------------------------------
__global__ void prep_kernel(const float* __restrict__ w_dp_f,
                            const float* __restrict__ w_proj) {
    const int r = blockIdx.x;          // 0..71
    const int k = threadIdx.x;         // 0..255
    float v = 0.f;
    if (r < HCH)      v = w_dp_f[r * CIN + k];
    else if (r < 70)  v = w_proj[(r - HCH) * CIN + k];
    g_Bw[r * B_STRIDE + ((k >> 3) << 3) + (k & 3) * 2 + ((k >> 2) & 1)] = to_tf32(v);
    if (k < 8) g_Bw[r * B_STRIDE + 256 + k] = 0u;
}

// ---------------------------------------------------------------------------
// Kernel A: PERSISTENT mma.sync tf32 GEMM. Grid = 144 CTAs, 8 tiles each.
// B copied to smem ONCE per CTA (amortized 8x vs per-tile CTAs).
// Per tile: 128 positions, double-buffered A (round-5 pipeline).
// ---------------------------------------------------------------------------
#define A_STRIDE 136
#define A_WORDS (64 * A_STRIDE)                       // 8704 per buffer
#define GEMM_SMEM ((B_WORDS + 2 * A_WORDS) * 4)       // 145,664 bytes

extern __shared__ uint32_t sm4[];

__global__ void __launch_bounds__(256, 1)
gemm_tc(const float* __restrict__ p_fea) {
    const int tid  = threadIdx.x;
    const int wid  = tid >> 5;
    const int lane = tid & 31;

    // ---- copy pre-packed B once (uint4)
    {
        uint4* dst = (uint4*)sm4;
        const uint4* src = (const uint4*)g_Bw;
#pragma unroll
        for (int i = 0; i < 19; ++i) {
            const int idx = tid + i * 256;
            if (idx < B_WORDS / 4) dst[idx] = src[idx];
        }
    }

    // loader role
    const int pos = tid & 127;
    const int kb  = tid >> 7;            // 0 or 1

    // MMA role
    const int mt = wid;                  // m-tile 0..7
    const int q  = lane >> 2;
    const int rr = lane & 3;
    const int arow = mt * 16 + q;

    uint32_t* Abuf0 = sm4 + B_WORDS;

#pragma unroll 1
    for (int t = 0; t < TILES_PER_CTA; ++t) {
        // consecutive tiles: CTA covers 1024 consecutive positions
        // (1024-aligned blocks never cross a batch: 9216 = 9*1024)
        const int tbase = (blockIdx.x * TILES_PER_CTA + t) * 128;
        const int b  = tbase / HWDIM;
        const int s0 = tbase - b * HWDIM;
        const float* gx = p_fea + (size_t)b * (CIN * HWDIM) + s0 + pos;

        float d[9][4];
#pragma unroll
        for (int nt = 0; nt < 9; ++nt)
#pragma unroll
            for (int j = 0; j < 4; ++j) d[nt][j] = 0.f;

        // prologue: chunk 0 -> regs -> buf0 (k-major: word = kl*136 + pos)
        // (safe: buf0's last reader was fenced by the previous tile's c=3
        //  top-of-loop barrier)
        float xr[32];
#pragma unroll
        for (int i = 0; i < 32; ++i)
            xr[i] = gx[(size_t)(kb + i * 2) * HWDIM];
#pragma unroll
        for (int i = 0; i < 32; ++i)
            Abuf0[(kb + i * 2) * A_STRIDE + pos] = to_tf32(xr[i]);

#pragma unroll 1
        for (int c = 0; c < 4; ++c) {
            uint32_t* Ac = sm4 + B_WORDS + (c & 1) * A_WORDS;
            uint32_t* An = sm4 + B_WORDS + ((c + 1) & 1) * A_WORDS;

            if (c < 3) {
#pragma unroll
                for (int i = 0; i < 32; ++i)
                    xr[i] = gx[(size_t)((c + 1) * 64 + kb + i * 2) * HWDIM];
            }
            __syncthreads();   // buf[c] (and B on first tile) ready

            // MMA over 8 k-steps of this chunk
#pragma unroll
            for (int ks = 0; ks < 8; ++ks) {
                const int kl = ks * 8 + rr;
                const uint32_t a0 = Ac[kl * A_STRIDE + arow];
                const uint32_t a1 = Ac[kl * A_STRIDE + arow + 8];
                const uint32_t a2 = Ac[(kl + 4) * A_STRIDE + arow];
                const uint32_t a3 = Ac[(kl + 4) * A_STRIDE + arow + 8];
                const int bbase = (c * 8 + ks) * 8 + rr * 2;
#pragma unroll
                for (int nt = 0; nt < 9; ++nt) {
                    const u64 b01 = *(const u64*)(sm4 + (nt * 8 + q) * B_STRIDE + bbase);
                    mma_tf32(d[nt], a0, a1, a2, a3,
                             (uint32_t)b01, (uint32_t)(b01 >> 32));
                }
            }

            if (c < 3) {
#pragma unroll
                for (int i = 0; i < 32; ++i)
                    An[(kb + i * 2) * A_STRIDE + pos] = to_tf32(xr[i]);
            }
        }

        // ---- store D to g_Y (fp16)
        const int pbase = tbase + mt * 16 + q;
#pragma unroll
        for (int nt = 0; nt < 9; ++nt) {
            const int n0 = nt * 8 + rr * 2;
            if (n0 < 70) {
                g_Y[n0 * NPOS + pbase]     = __float2half(d[nt][0]);
                g_Y[n0 * NPOS + pbase + 8] = __float2half(d[nt][2]);
            }
            if (n0 + 1 < 70) {
                g_Y[(n0 + 1) * NPOS + pbase]     = __float2half(d[nt][1]);
                g_Y[(n0 + 1) * NPOS + pbase + 8] = __float2half(d[nt][3]);
            }
        }
        // next tile's prologue STS to buf0 is fenced by this tile's c=3
        // barrier (all buf0 reads completed at c=2, barrier at c=3 top).
        __syncthreads();
    }
}

// ---------------------------------------------------------------------------
// Kernel B (round-14 exact): epilogue with smem xq cache.
// ---------------------------------------------------------------------------
#define EPI_CW 2224
#define EPI_SMEM ((EPI_CW + 60 * 256) * 4)    // 70,336 bytes

__global__ void __launch_bounds__(256, 2)
epi_kernel(const float* __restrict__ xp_stack,
           const float* __restrict__ xh_stack,
           const float* __restrict__ w_att,  const float* __restrict__ b_att,
           const float* __restrict__ w_dp_x, const float* __restrict__ b_dp,
           const float* __restrict__ b_proj,
           const float* __restrict__ w_gate, const float* __restrict__ b_gate,
           const float* __restrict__ w_upd,  const float* __restrict__ b_upd,
           float* __restrict__ out) {
    float* cw  = (float*)sm4;
    float* xqc = cw + EPI_CW;
    const int tid = threadIdx.x;

    for (int i = tid; i < 2222; i += 256) {
        float v;
        if      (i < 60)   v = w_att[i];
        else if (i < 66)   v = b_att[i - 60];
        else if (i < 166)  v = w_dp_x[i - 66];
        else if (i < 176)  v = b_dp[i - 166];
        else if (i < 236)  v = b_proj[i - 176];
        else if (i < 356)  v = w_gate[i - 236];
        else if (i < 362)  v = b_gate[i - 356];
        else if (i < 2162) v = w_upd[i - 362];
        else               v = b_upd[i - 2162];
        cw[i] = v;
    }
    __syncthreads();

    const float* sW_att  = cw;
    const float* sB_att  = cw + 60;
    const float* sW_dpx  = cw + 66;
    const float* sB_dp   = cw + 166;
    const float* sB_proj = cw + 176;
    const float* sW_gate = cw + 236;
    const float* sB_gate = cw + 356;
    const float* sW_upd  = cw + 362;
    const float* sB_upd  = cw + 2162;

    const int n = blockIdx.x * 256 + tid;
    const int b = n / HWDIM;
    const int s = n - b * HWDIM;
    const int bbase = b * (HCH * HWDIM) + s;

    float fdp[HCH];
#pragma unroll
    for (int d = 0; d < HCH; ++d)
        fdp[d] = __half2float(g_Y[d * NPOS + n]) + sB_dp[d];

    float att[NPARTS];
    float dp1[HCH], S[HCH], xp1[HCH];
    float attsum = 0.f;
#pragma unroll
    for (int d = 0; d < HCH; ++d) S[d] = 0.f;

    // ---- pass 1: load xq from gmem once, stash in smem
#pragma unroll
    for (int p = 0; p < NPARTS; ++p) {
        const float* xpp_ptr = xp_stack + p * PBH + bbase;
        float xq[HCH];
#pragma unroll
        for (int d = 0; d < HCH; ++d) {
            xq[d] = xpp_ptr[d * HWDIM];
            xqc[(p * HCH + d) * 256 + tid] = xq[d];
        }

        float a = sB_att[p];
#pragma unroll
        for (int d = 0; d < HCH; ++d) a += sW_att[p * HCH + d] * xq[d];
        a = sigm(a);
        att[p] = a;

        float dpv[HCH];
#pragma unroll
        for (int d = 0; d < HCH; ++d) {
            float u = fdp[d];
#pragma unroll
            for (int e = 0; e < HCH; ++e) u += sW_dpx[d * HCH + e] * xq[e];
            dpv[d] = fmaxf(u, 0.f);
        }
        if (p == 1) {
#pragma unroll
            for (int d = 0; d < HCH; ++d) { dp1[d] = dpv[d]; xp1[d] = xq[d]; }
        } else {
            attsum += a;
#pragma unroll
            for (int d = 0; d < HCH; ++d) S[d] += a * dpv[d];
        }
    }

    // ---- pass 2: xq from smem
#pragma unroll
    for (int p = 0; p < NPARTS; ++p) {
        float xq[HCH];
        if (p == 1) {
#pragma unroll
            for (int d = 0; d < HCH; ++d) xq[d] = xp1[d];
        } else {
#pragma unroll
            for (int d = 0; d < HCH; ++d) xq[d] = xqc[(p * HCH + d) * 256 + tid];
        }

        float xppv[HCH];
        if (p == 1) {
#pragma unroll
            for (int d = 0; d < HCH; ++d)
                xppv[d] = att[1] * (S[d] + attsum * xp1[d]);
        } else {
            const float aa = att[1] * att[p];
#pragma unroll
            for (int d = 0; d < HCH; ++d)
                xppv[d] = aa * (dp1[d] + xq[d]);
        }

        const int hf = (p < 4) ? 0 : 1;
        const float* xh_ptr = xh_stack + hf * PBH + bbase;
        float gsum = sB_gate[p];
#pragma unroll
        for (int d = 0; d < HCH; ++d)
            gsum += sW_gate[p * 2 * HCH + d] * xh_ptr[d * HWDIM];
#pragma unroll
        for (int d = 0; d < HCH; ++d)
            gsum += sW_gate[p * 2 * HCH + HCH + d] * xq[d];
        const float gate = sigm(gsum);

        float xhpv[HCH];
#pragma unroll
        for (int d = 0; d < HCH; ++d)
            xhpv[d] = gate * (__half2float(g_Y[(HCH + p * HCH + d) * NPOS + n])
                              + sB_proj[p * HCH + d]);

        float* o0 = out + p * PBH + bbase;
#pragma unroll
        for (int d = 0; d < HCH; ++d) {
            float u = sB_upd[p * HCH + d];
            const float* wr = sW_upd + (p * HCH + d) * (3 * HCH);
#pragma unroll
            for (int e = 0; e < HCH; ++e) u += wr[e] * xq[e];
#pragma unroll
            for (int e = 0; e < HCH; ++e) u += wr[HCH + e] * xppv[e];
#pragma unroll
            for (int e = 0; e < HCH; ++e) u += wr[2 * HCH + e] * xhpv[e];
            const float o = xq[d] + fmaxf(u, 0.f);

            const int doff = d * HWDIM;
            o0[doff]                = o;
            o0[PART_SZ + doff]      = xppv[d];
            o0[2 * PART_SZ + doff]  = xhpv[d];
        }
    }
}

// ---------------------------------------------------------------------------
extern "C" void kernel_launch(void* const* d_in, const int* in_sizes, int n_in,
                              void* d_out, int out_size) {
    const float* p_fea  = (const float*)d_in[0];
    const float* xp     = (const float*)d_in[1];
    const float* xh     = (const float*)d_in[2];
    const float* w_att  = (const float*)d_in[3];
    const float* b_att  = (const float*)d_in[4];
    const float* w_dp_f = (const float*)d_in[5];
    const float* w_dp_x = (const float*)d_in[6];
    const float* b_dp   = (const float*)d_in[7];
    const float* w_proj = (const float*)d_in[8];
    const float* b_proj = (const float*)d_in[9];
    const float* w_gate = (const float*)d_in[10];
    const float* b_gate = (const float*)d_in[11];
    const float* w_upd  = (const float*)d_in[12];
    const float* b_upd  = (const float*)d_in[13];
    float* out = (float*)d_out;

    cudaFuncSetAttribute(gemm_tc, cudaFuncAttributeMaxDynamicSharedMemorySize,
                         GEMM_SMEM);
    cudaFuncSetAttribute(epi_kernel, cudaFuncAttributeMaxDynamicSharedMemorySize,
                         EPI_SMEM);

    prep_kernel<<<72, 256>>>(w_dp_f, w_proj);
    gemm_tc<<<GEMM_GRID, 256, GEMM_SMEM>>>(p_fea);
    epi_kernel<<<NPOS / 256, 256, EPI_SMEM>>>(xp, xh, w_att, b_att, w_dp_x, b_dp,
                                              b_proj, w_gate, b_gate, w_upd, b_upd, out);
}